// round 15
// baseline (speedup 1.0000x reference)
#include <cuda_runtime.h>

// VectorQuantizer: z_e [32,64,32,32] f32, emb [1024,64] f32
// out (f32): z_st [2097152], loss, perplexity, encodings [32768 x 1024]

#define ND 64
#define NK 1024
#define NCP 512                       // code pairs
#define HW 1024
#define NN 32768
#define ZELEMS 2097152
#define ROWS 16                       // rows per block
#define NBLK (NN / ROWS)              // 2048

typedef unsigned long long u64;

__device__ u64    g_embT[ND * NCP + 1024];  // [d][cp]=(e_{2cp,d},e_{2cp+1,d}) + pad
__device__ float  g_e2[NK];
__device__ float  g_a[NN];                  // ||x_n||^2
__device__ int    g_counts[NK];
__device__ double g_losspart[NBLK];

static __device__ __forceinline__ u64 pk2(float lo, float hi) {
    u64 r;
    asm("mov.b64 %0, {%1, %2};" : "=l"(r) : "f"(lo), "f"(hi));
    return r;
}
static __device__ __forceinline__ void upk2(u64 v, float& lo, float& hi) {
    asm("mov.b64 {%0, %1}, %2;" : "=f"(lo), "=f"(hi) : "l"(v));
}
static __device__ __forceinline__ void fma2(u64& acc, u64 a, u64 b) {
    asm("fma.rn.f32x2 %0, %1, %2, %0;" : "+l"(acc) : "l"(a), "l"(b));
}
static __device__ __forceinline__ u64 umin64(u64 a, u64 b) { return a < b ? a : b; }

// ---------------------------------------------------------------------------
// launch 0 — embT table build (+ prefetch pad). Pure copy. grid 132 x 256
// ---------------------------------------------------------------------------
__global__ void vq_prep_embT(const float* __restrict__ emb) {
    const int t = blockIdx.x * 256 + threadIdx.x;       // 0..33791
    if (t < ND * NCP) {
        const int d = t >> 9, cp = t & (NCP - 1);
        g_embT[t] = pk2(emb[(2 * cp) * ND + d], emb[(2 * cp + 1) * ND + d]);
    } else {
        g_embT[t] = 0ULL;                               // prefetch pad
    }
}

// ---------------------------------------------------------------------------
// launch 1 — e2 (fp64 4-chain, order identical to all passing rounds)
// + counts zero. grid 4 x 256
// ---------------------------------------------------------------------------
__global__ void vq_prep_e2(const float* __restrict__ emb) {
    const int t = blockIdx.x * 256 + threadIdx.x;       // 0..1023
    g_counts[t] = 0;
    const float* er = emb + t * ND;
    double s0 = 0.0, s1 = 0.0, s2 = 0.0, s3 = 0.0;
#pragma unroll
    for (int i = 0; i < 16; i++) {
        double a = (double)er[4 * i],     b = (double)er[4 * i + 1];
        double c = (double)er[4 * i + 2], dd = (double)er[4 * i + 3];
        s0 += a * a; s1 += b * b; s2 += c * c; s3 += dd * dd;
    }
    g_e2[t] = (float)((s0 + s1) + (s2 + s3));
}

// ---------------------------------------------------------------------------
// launch 2 — row sumsq ||x||^2 (round-8 4-chain scheme; rel_err-verified).
// grid 128 x 256
// ---------------------------------------------------------------------------
__global__ void vq_prep_rows(const float* __restrict__ ze) {
    const int t = blockIdx.x * 256 + threadIdx.x;       // 0..32767
    const int b = t >> 10, hw = t & (HW - 1);
    const float* zp = ze + (size_t)b * ND * HW + hw;
    double s0 = 0.0, s1 = 0.0, s2 = 0.0, s3 = 0.0;
#pragma unroll
    for (int i = 0; i < 16; i++) {
        double a = (double)zp[(size_t)(4 * i) * HW];
        double c = (double)zp[(size_t)(4 * i + 1) * HW];
        double d = (double)zp[(size_t)(4 * i + 2) * HW];
        double e = (double)zp[(size_t)(4 * i + 3) * HW];
        s0 += a * a; s1 += c * c; s2 += d * d; s3 += e * e;
    }
    g_a[t] = (float)((s0 + s1) + (s2 + s3));  // binade-offset vs ref: argmin-invariant
}

// ---------------------------------------------------------------------------
// launch 3 (PROFILED) — fused main: 16 rows x all 1024 codes per block.
// GEMM phase identical to round 14; sa phase replaced by g_a load.
// grid 2048 x 256.
// ---------------------------------------------------------------------------
__global__ __launch_bounds__(256, 2) void vq_main(const float* __restrict__ ze,
                                                  const float* __restrict__ emb,
                                                  float* __restrict__ out) {
    __shared__ u64    xs[ROWS * ND];     // [row][d] = (x,x), 8 KB
    __shared__ float  sa[ROWS];          // ||x||^2 (from g_a)
    __shared__ u64    swb[8 * ROWS];     // per-warp best keys
    __shared__ int    scode[ROWS];
    __shared__ double red[256];

    const int tid  = threadIdx.x;
    const int w    = tid >> 5;
    const int g    = tid & 31;
    const int row0 = blockIdx.x * ROWS;
    const int b    = row0 >> 10;
    const int hw0  = row0 & (HW - 1);

    // ---- stage x tile duplicated: xs[r][d] = (x,x)
    const float* zbase = ze + (size_t)b * ND * HW + hw0;
#pragma unroll
    for (int i = 0; i < 4; i++) {
        const int idx = tid + i * 256;
        const int d = idx >> 4, r = idx & (ROWS - 1);
        const float x = zbase[(size_t)d * HW + r];
        xs[r * ND + d] = pk2(x, x);
    }
    if (tid < ROWS) sa[tid] = g_a[row0 + tid];

    // ---- encodings zero-fill for this block's 16 rows (fire-and-forget)
    float* encrow = out + (size_t)ZELEMS + 2 + (size_t)row0 * NK;
    if (tid == 0) {
        *(float2*)encrow = make_float2(0.0f, 0.0f);                    // lead 2
        *(float2*)(encrow + ROWS * NK - 2) = make_float2(0.0f, 0.0f);  // tail 2
    }
    {
        float4* p = (float4*)(encrow + 2);             // 4095 aligned slots
        const float4 z4 = make_float4(0.0f, 0.0f, 0.0f, 0.0f);
#pragma unroll
        for (int j = 0; j < 16; j++) {
            const int s = tid + j * 256;
            if (s < 4095) p[s] = z4;
        }
    }
    __syncthreads();

    // ---- GEMM: acc[r][c] over d, sequential (bit-identical rounding)
    const u64* __restrict__ bq = g_embT + w * 64 + g;
    const u64* xr0 = xs;

    u64 acc[ROWS * 2];
#pragma unroll
    for (int i = 0; i < ROWS * 2; i++) acc[i] = 0ULL;

    u64 bA[4], bB[4];
#pragma unroll
    for (int c = 0; c < 2; c++) {                      // d2 = 0
        bA[c]     = bq[32 * c];
        bA[2 + c] = bq[512 + 32 * c];
    }
#pragma unroll 2
    for (int d2 = 0; d2 < ND / 2; d2++) {
        u64* cur = (d2 & 1) ? bB : bA;
        u64* nxt = (d2 & 1) ? bA : bB;
        const u64* bqn = bq + (size_t)(2 * d2 + 2) * 512;   // pad covers d2=31
#pragma unroll
        for (int c = 0; c < 2; c++) {                  // prefetch next d-pair
            nxt[c]     = bqn[32 * c];
            nxt[2 + c] = bqn[512 + 32 * c];
        }
#pragma unroll
        for (int r = 0; r < ROWS; r++) {
            const ulonglong2 av = *(const ulonglong2*)(xr0 + r * ND + 2 * d2);  // bcast
            fma2(acc[r * 2 + 0], av.x, cur[0]);
            fma2(acc[r * 2 + 1], av.x, cur[1]);
            fma2(acc[r * 2 + 0], av.y, cur[2]);
            fma2(acc[r * 2 + 1], av.y, cur[3]);
        }
    }

    // ---- dist + per-thread min (keys keep lowest code on ties)
    u64 bestk[ROWS];
#pragma unroll
    for (int r = 0; r < ROWS; r++) bestk[r] = 0xFFFFFFFFFFFFFFFFULL;
#pragma unroll
    for (int c = 0; c < 2; c++) {
        const int code0 = 2 * (w * 64 + 32 * c + g);
        const float2 e2p = *(const float2*)(g_e2 + code0);
#pragma unroll
        for (int r = 0; r < ROWS; r++) {
            float dot0, dot1;
            upk2(acc[r * 2 + c], dot0, dot1);
            const float dist0 = fmaf(-2.0f, dot0, sa[r] + e2p.x);  // ref combine order
            const float dist1 = fmaf(-2.0f, dot1, sa[r] + e2p.y);
            const u64 k0 = ((u64)__float_as_uint(dist0) << 32) | (unsigned)code0;
            const u64 k1 = ((u64)__float_as_uint(dist1) << 32) | (unsigned)(code0 + 1);
            bestk[r] = umin64(bestk[r], umin64(k0, k1));
        }
    }
    // lane reduce (disjoint codes per lane)
#pragma unroll
    for (int off = 16; off > 0; off >>= 1)
#pragma unroll
        for (int r = 0; r < ROWS; r++)
            bestk[r] = umin64(bestk[r], __shfl_down_sync(0xFFFFFFFFu, bestk[r], off));
    if (g == 0) {
#pragma unroll
        for (int r = 0; r < ROWS; r++) swb[w * ROWS + r] = bestk[r];
    }
    __syncthreads();          // also orders zero-fill before the one-hot writes

    // cross-warp reduce -> final codes; counts + one-hot
    if (tid < ROWS) {
        u64 m = swb[tid];
#pragma unroll
        for (int ww = 1; ww < 8; ww++) m = umin64(m, swb[ww * ROWS + tid]);
        const int code = (int)(m & 0xFFFFFFFFULL);
        scode[tid] = code;
        atomicAdd(&g_counts[code], 1);
        encrow[(size_t)tid * NK + code] = 1.0f;
    }
    __syncthreads();

    // ---- z_st + loss partials (4 elements per thread)
    float* op = out + (size_t)b * ND * HW + hw0;
    double ls = 0.0;
#pragma unroll
    for (int j = 0; j < 4; j++) {
        const int e = tid + j * 256;
        const int d = e >> 4, r = e & (ROWS - 1);
        float x, xh;
        upk2(xs[r * ND + d], x, xh);
        const float q = emb[(size_t)scode[r] * ND + d];
        const float df = q - x;
        op[(size_t)d * HW + r] = x + df;        // z + (z_q - z), both fp32 roundings
        const float sq = df * df;
        ls += (double)sq;
    }
    red[tid] = ls;
    __syncthreads();
    for (int st = 128; st > 0; st >>= 1) {
        if (tid < st) red[tid] += red[tid + st];
        __syncthreads();
    }
    if (tid == 0) g_losspart[blockIdx.x] = red[0];
}

// ---------------------------------------------------------------------------
// launch 4 — finalize: loss + perplexity. 1 x 256
// ---------------------------------------------------------------------------
__global__ void vq_fin(float* __restrict__ out) {
    __shared__ double se[256];
    __shared__ double sl[256];
    const int t = threadIdx.x;
    double ent = 0.0;
#pragma unroll
    for (int i = 0; i < 4; i++) {
        const int k = t + 256 * i;
        const float p = (float)g_counts[k] / (float)NN;
        ent += (double)(p * logf(p + 1e-10f));
    }
    double ll = 0.0;
#pragma unroll
    for (int i = 0; i < 8; i++) ll += g_losspart[t + 256 * i];   // fixed order
    se[t] = ent;
    sl[t] = ll;
    __syncthreads();
    for (int st = 128; st > 0; st >>= 1) {
        if (t < st) { se[t] += se[t + st]; sl[t] += sl[t + st]; }
        __syncthreads();
    }
    if (t == 0) {
        const float m = (float)(sl[0] / (double)ZELEMS);  // q_latent == e_latent
        out[ZELEMS]     = m + 0.25f * m;
        out[ZELEMS + 1] = expf(-(float)se[0]);
    }
}

extern "C" void kernel_launch(void* const* d_in, const int* in_sizes, int n_in,
                              void* d_out, int out_size) {
    const float* ze  = (const float*)d_in[0];
    const float* emb = (const float*)d_in[1];
    float*       out = (float*)d_out;

    vq_prep_embT<<<132, 256>>>(emb);    // 0
    vq_prep_e2<<<4, 256>>>(emb);        // 1
    vq_prep_rows<<<128, 256>>>(ze);     // 2
    vq_main<<<NBLK, 256>>>(ze, emb, out);  // 3 <- ncu captures this
    vq_fin<<<1, 256>>>(out);            // 4
}

// round 17
// speedup vs baseline: 1.1607x; 1.1607x over previous
#include <cuda_runtime.h>

// VectorQuantizer: z_e [32,64,32,32] f32, emb [1024,64] f32
// out (f32): z_st [2097152], loss, perplexity, encodings [32768 x 1024]
// (round-16 candidate resubmitted verbatim after infra failure; OOB/hang
//  audit clean: max prefetch index 34791 < 34816, losspart idx < 4096)

#define ND 64
#define NK 1024
#define HW 1024
#define NN 32768
#define ZELEMS 2097152
#define ROWS 8                        // rows per block
#define NBLK (NN / ROWS)              // 4096

typedef unsigned long long u64;

__device__ u64    g_embT[32 * NK + 2048];   // [dp][k]=(e_{k,2dp},e_{k,2dp+1}) + pad
__device__ float  g_e2[NK];
__device__ int    g_counts[NK];
__device__ double g_losspart[NBLK];

static __device__ __forceinline__ void upk2(u64 v, float& lo, float& hi) {
    asm("mov.b64 {%0, %1}, %2;" : "=f"(lo), "=f"(hi) : "l"(v));
}
static __device__ __forceinline__ void fma2(u64& acc, u64 a, u64 b) {
    asm("fma.rn.f32x2 %0, %1, %2, %0;" : "+l"(acc) : "l"(a), "l"(b));
}
static __device__ __forceinline__ u64 umin64(u64 a, u64 b) { return a < b ? a : b; }

// ---------------------------------------------------------------------------
// prep: d-pair embT table (+pad) + e2 + counts. grid 272 x 128 = 34816
// ---------------------------------------------------------------------------
__global__ void vq_prep(const float* __restrict__ emb) {
    const int t = blockIdx.x * 128 + threadIdx.x;       // 0..34815
    if (t < 32 * NK) {
        const int dp = t >> 10, k = t & (NK - 1);
        g_embT[t] = ((const u64*)emb)[k * 32 + dp];     // natural d-pair
    } else {
        g_embT[t] = 0ULL;                               // prefetch pad (2 dp rows)
    }
    if (t < NK) {
        g_counts[t] = 0;
        const float* er = emb + t * ND;
        double s0 = 0.0, s1 = 0.0, s2 = 0.0, s3 = 0.0;  // 4 chains
#pragma unroll
        for (int i = 0; i < 16; i++) {
            double a = (double)er[4 * i],     b = (double)er[4 * i + 1];
            double c = (double)er[4 * i + 2], dd = (double)er[4 * i + 3];
            s0 += a * a; s1 += b * b; s2 += c * c; s3 += dd * dd;
        }
        g_e2[t] = (float)((s0 + s1) + (s2 + s3));
    }
}

// ---------------------------------------------------------------------------
// fused main: block = 8 rows x ALL 1024 codes. Warp w owns codes
// [w*128, w*128+128): lane g, slots c -> code = w*128 + 32c + g (disjoint).
// Thread tile = 8 rows x 4 codes. x UNDUPLICATED in smem: one broadcast
// LDS.128 = 4 d's. b = natural d-pair u64 from embT (coalesced), 1-dp2-ahead
// double-buffered prefetch. acc f32x2 = (even-d chain, odd-d chain), dp
// ascending; dot = lo+hi (round-5-verified rounding). In-block argmin +
// fused epilogue. grid 4096 x 256.
// ---------------------------------------------------------------------------
__global__ __launch_bounds__(256, 2) void vq_main(const float* __restrict__ ze,
                                                  const float* __restrict__ emb,
                                                  float* __restrict__ out) {
    __shared__ float  xs[ROWS * ND];     // [row][d], 2 KB, unduplicated
    __shared__ float  sa[ROWS];          // ||x||^2
    __shared__ double sred[32];
    __shared__ u64    swb[8 * ROWS];     // per-warp best keys
    __shared__ int    scode[ROWS];
    __shared__ double red[256];

    const int tid  = threadIdx.x;
    const int w    = tid >> 5;
    const int g    = tid & 31;
    const int row0 = blockIdx.x * ROWS;
    const int b    = row0 >> 10;
    const int hw0  = row0 & (HW - 1);

    // ---- stage x tile: xs[r][d] = ze[b][d][hw0+r] (2 elems/thread)
    const float* zbase = ze + (size_t)b * ND * HW + hw0;
#pragma unroll
    for (int i = 0; i < 2; i++) {
        const int idx = tid + i * 256;
        const int d = idx >> 3, r = idx & (ROWS - 1);
        xs[r * ND + d] = zbase[(size_t)d * HW + r];
    }

    // ---- encodings zero-fill for this block's 8 rows (fire-and-forget)
    float* encrow = out + (size_t)ZELEMS + 2 + (size_t)row0 * NK;
    if (tid == 0) {
        *(float2*)encrow = make_float2(0.0f, 0.0f);                    // floats 0,1
        *(float2*)(encrow + ROWS * NK - 2) = make_float2(0.0f, 0.0f);  // 8190,8191
    }
    {
        float4* p = (float4*)(encrow + 2);             // 2047 aligned slots
        const float4 z4 = make_float4(0.0f, 0.0f, 0.0f, 0.0f);
#pragma unroll
        for (int j = 0; j < 8; j++) {
            const int s = tid + j * 256;
            if (s < 2047) p[s] = z4;
        }
    }
    __syncthreads();

    // ---- ||x||^2: 32 threads, 4 x 16-d segments per row, fp64
    if (tid < 32) {
        const int r = tid & (ROWS - 1), seg = tid >> 3;
        const float* xr = xs + r * ND + seg * 16;
        double s = 0.0;
#pragma unroll
        for (int i = 0; i < 16; i++) { double v = (double)xr[i]; s += v * v; }
        sred[tid] = s;
    }
    __syncthreads();
    if (tid < ROWS)
        sa[tid] = (float)(((sred[tid] + sred[tid + 8]) + sred[tid + 16]) + sred[tid + 24]);
    __syncthreads();

    // ---- GEMM
    const u64* __restrict__ bq = g_embT + w * 128 + g;   // + dp*1024 + 32c

    u64 acc[ROWS * 4];                   // [r][c]
#pragma unroll
    for (int i = 0; i < ROWS * 4; i++) acc[i] = 0ULL;

    u64 bA[8], bB[8];                    // [c] for dp even, [4+c] for dp odd
#pragma unroll
    for (int c = 0; c < 4; c++) {        // dp2 = 0: dp 0,1
        bA[c]     = bq[32 * c];
        bA[4 + c] = bq[1024 + 32 * c];
    }
#pragma unroll 2
    for (int dp2 = 0; dp2 < 16; dp2++) {
        u64* cur = (dp2 & 1) ? bB : bA;
        u64* nxt = (dp2 & 1) ? bA : bB;
        const u64* bqn = bq + (size_t)(2 * dp2 + 2) * 1024;  // pad covers dp2=15
#pragma unroll
        for (int c = 0; c < 4; c++) {    // prefetch next dp pair
            nxt[c]     = bqn[32 * c];
            nxt[4 + c] = bqn[1024 + 32 * c];
        }
#pragma unroll
        for (int r = 0; r < ROWS; r++) {
            // broadcast LDS.128: 4 d's = (x0,x1),(x2,x3)
            const ulonglong2 av = *(const ulonglong2*)(xs + r * ND + 4 * dp2);
#pragma unroll
            for (int c = 0; c < 4; c++) fma2(acc[r * 4 + c], av.x, cur[c]);
#pragma unroll
            for (int c = 0; c < 4; c++) fma2(acc[r * 4 + c], av.y, cur[4 + c]);
        }
    }

    // ---- dist + per-thread min (keys keep lowest code on ties)
    u64 bestk[ROWS];
#pragma unroll
    for (int r = 0; r < ROWS; r++) bestk[r] = 0xFFFFFFFFFFFFFFFFULL;
#pragma unroll
    for (int c = 0; c < 4; c++) {
        const int code = w * 128 + 32 * c + g;
        const float e2 = g_e2[code];
#pragma unroll
        for (int r = 0; r < ROWS; r++) {
            float lo, hi;
            upk2(acc[r * 4 + c], lo, hi);
            const float dot  = lo + hi;                       // round-5-verified
            const float dist = fmaf(-2.0f, dot, sa[r] + e2);  // ref combine order
            const u64 key = ((u64)__float_as_uint(dist) << 32) | (unsigned)code;
            bestk[r] = umin64(bestk[r], key);
        }
    }
    // lane reduce (disjoint codes per lane)
#pragma unroll
    for (int off = 16; off > 0; off >>= 1)
#pragma unroll
        for (int r = 0; r < ROWS; r++)
            bestk[r] = umin64(bestk[r], __shfl_down_sync(0xFFFFFFFFu, bestk[r], off));
    if (g == 0) {
#pragma unroll
        for (int r = 0; r < ROWS; r++) swb[w * ROWS + r] = bestk[r];
    }
    __syncthreads();          // also orders zero-fill before the one-hot writes

    // cross-warp reduce -> final codes; counts + one-hot
    if (tid < ROWS) {
        u64 m = swb[tid];
#pragma unroll
        for (int ww = 1; ww < 8; ww++) m = umin64(m, swb[ww * ROWS + tid]);
        const int code = (int)(m & 0xFFFFFFFFULL);
        scode[tid] = code;
        atomicAdd(&g_counts[code], 1);
        encrow[(size_t)tid * NK + code] = 1.0f;
    }
    __syncthreads();

    // ---- z_st + loss partials (2 elements per thread)
    float* op = out + (size_t)b * ND * HW + hw0;
    double ls = 0.0;
#pragma unroll
    for (int j = 0; j < 2; j++) {
        const int e = tid + j * 256;
        const int d = e >> 3, r = e & (ROWS - 1);
        const float x = xs[r * ND + d];
        const float q = emb[(size_t)scode[r] * ND + d];
        const float df = q - x;
        op[(size_t)d * HW + r] = x + df;        // z + (z_q - z), both fp32 roundings
        const float sq = df * df;
        ls += (double)sq;
    }
    red[tid] = ls;
    __syncthreads();
    for (int st = 128; st > 0; st >>= 1) {
        if (tid < st) red[tid] += red[tid + st];
        __syncthreads();
    }
    if (tid == 0) g_losspart[blockIdx.x] = red[0];
}

// ---------------------------------------------------------------------------
// finalize: loss + perplexity. 1 x 256
// ---------------------------------------------------------------------------
__global__ void vq_fin(float* __restrict__ out) {
    __shared__ double se[256];
    __shared__ double sl[256];
    const int t = threadIdx.x;
    double ent = 0.0;
#pragma unroll
    for (int i = 0; i < 4; i++) {
        const int k = t + 256 * i;
        const float p = (float)g_counts[k] / (float)NN;
        ent += (double)(p * logf(p + 1e-10f));
    }
    double ll = 0.0;
#pragma unroll
    for (int i = 0; i < 16; i++) ll += g_losspart[t + 256 * i];  // fixed order
    se[t] = ent;
    sl[t] = ll;
    __syncthreads();
    for (int st = 128; st > 0; st >>= 1) {
        if (t < st) { se[t] += se[t + st]; sl[t] += sl[t + st]; }
        __syncthreads();
    }
    if (t == 0) {
        const float m = (float)(sl[0] / (double)ZELEMS);  // q_latent == e_latent
        out[ZELEMS]     = m + 0.25f * m;
        out[ZELEMS + 1] = expf(-(float)se[0]);
    }
}

extern "C" void kernel_launch(void* const* d_in, const int* in_sizes, int n_in,
                              void* d_out, int out_size) {
    const float* ze  = (const float*)d_in[0];
    const float* emb = (const float*)d_in[1];
    float*       out = (float*)d_out;

    vq_prep<<<272, 128>>>(emb);
    vq_main<<<NBLK, 256>>>(ze, emb, out);
    vq_fin<<<1, 256>>>(out);
}